// round 6
// baseline (speedup 1.0000x reference)
#include <cuda_runtime.h>
#include <cuda_bf16.h>
#include <cstdint>

#define B_ 16
#define T_ 2048
#define L_ 128
#define H_ 512
#define M_IN 256
#define F_ 1024
#define LP 130                 // 128 ch + 1 const + 1 pad
#define C_CHUNK 16
#define Q_CHUNK 16
#define KTOT (C_CHUNK * LP)    // 2080
#define MZ (Q_CHUNK * B_)      // 256
#define NSPLIT 8
#define KPER 288               // 7*288=2016, last slice 64 (mult of 32)
#define SCAN_BLOCKS 64

typedef __nv_bfloat16 bf16;

__device__ __align__(16) bf16 g_A0h[H_ * H_], g_A0l[H_ * H_];
__device__ __align__(16) bf16 g_Uh[KTOT * H_], g_Ul[KTOT * H_];
__device__ __align__(16) bf16 g_Ph[4 * H_ * H_], g_Pl[4 * H_ * H_];
__device__ __align__(16) bf16 g_Xh[MZ * KTOT], g_Xl[MZ * KTOT];
__device__ __align__(16) float g_Gf[H_ * H_];
__device__ __align__(16) float g_Zp[NSPLIT * MZ * H_];
__device__ __align__(16) float g_S0[B_ * H_], g_S1[B_ * H_];
__device__ int g_cnt;
__device__ int g_gen;

__device__ __forceinline__ void splitw(float v, bf16* ph, bf16* pl) {
    bf16 h = __float2bfloat16(v);
    *ph = h;
    *pl = __float2bfloat16(v - __bfloat162float(h));
}

// ------------------------- merged prep kernel ------------------------------
// blocks [0,1024): splitA; [1024,1284): initW0; [1284,3364): gather; b0: barinit
__global__ void k_prep(const float* __restrict__ A, const float* __restrict__ We,
                       const float* __restrict__ be, const float* __restrict__ Wb,
                       const float* __restrict__ x) {
    const int NB_A = (H_ * H_) / 256;          // 1024
    const int NB_W = (LP * H_ + 255) / 256;    // 260
    int bid = blockIdx.x, tid = threadIdx.x;
    if (bid == 0 && tid == 0) { g_cnt = 0; g_gen = 0; }
    if (bid < NB_A) {
        int i = bid * 256 + tid;
        splitw(A[i], &g_A0h[i], &g_A0l[i]);
    } else if (bid < NB_A + NB_W) {
        int i = (bid - NB_A) * 256 + tid;
        if (i >= LP * H_) return;
        int l = i >> 9, h = i & 511;
        float acc = 0.f;
        if (l < 128) { for (int m = 0; m < M_IN; m++) acc += We[l * M_IN + m] * Wb[m * H_ + h]; }
        else if (l == 128) { for (int m = 0; m < M_IN; m++) acc += be[m] * Wb[m * H_ + h]; }
        splitw(acc, &g_Uh[i], &g_Ul[i]);
    } else {
        int i = (bid - NB_A - NB_W) * 256 + tid;
        if (i >= MZ * KTOT) return;
        int m = i / KTOT, kk = i - m * KTOT;
        int r = kk / LP, l = kk - r * LP;
        int q = m >> 4, b = m & 15;
        float v;
        if (l < 128) v = x[((size_t)b * T_ + (T_ - 1) - (q * C_CHUNK + r)) * L_ + l];
        else v = (l == 128) ? 1.0f : 0.0f;
        splitw(v, &g_Xh[i], &g_Xl[i]);
    }
}

// ---------------------------------------------------------------------------
__device__ __forceinline__ void ldsm4(uint32_t* r, const void* p) {
    uint32_t addr = (uint32_t)__cvta_generic_to_shared(p);
    asm volatile("ldmatrix.sync.aligned.m8n8.x4.shared.b16 {%0,%1,%2,%3}, [%4];"
                 : "=r"(r[0]), "=r"(r[1]), "=r"(r[2]), "=r"(r[3]) : "r"(addr));
}
__device__ __forceinline__ void ldsm4t(uint32_t* r, const void* p) {
    uint32_t addr = (uint32_t)__cvta_generic_to_shared(p);
    asm volatile("ldmatrix.sync.aligned.m8n8.x4.trans.shared.b16 {%0,%1,%2,%3}, [%4];"
                 : "=r"(r[0]), "=r"(r[1]), "=r"(r[2]), "=r"(r[3]) : "r"(addr));
}
__device__ __forceinline__ void mma16816(float* d, const uint32_t* a, const uint32_t* b) {
    asm volatile("mma.sync.aligned.m16n8k16.row.col.f32.bf16.bf16.f32 "
                 "{%0,%1,%2,%3}, {%4,%5,%6,%7}, {%8,%9}, {%0,%1,%2,%3};"
                 : "+f"(d[0]), "+f"(d[1]), "+f"(d[2]), "+f"(d[3])
                 : "r"(a[0]), "r"(a[1]), "r"(a[2]), "r"(a[3]), "r"(b[0]), "r"(b[1]));
}
__device__ __forceinline__ void cpa16(uint32_t dst, const void* src, int srcsize) {
    asm volatile("cp.async.cg.shared.global [%0], [%1], 16, %2;"
                 :: "r"(dst), "l"(src), "r"(srcsize));
}
__device__ __forceinline__ void cpa_commit() { asm volatile("cp.async.commit_group;"); }
__device__ __forceinline__ void cpa_wait1() { asm volatile("cp.async.wait_group 1;"); }
__device__ __forceinline__ void cpa_wait0() { asm volatile("cp.async.wait_group 0;"); }

// dynamic smem layout (bf16 elements):
// Ash [2][5120]  @0        (128 rows x 40 stride)
// Asl [2][5120]  @10240
// Bsh [2][2304]  @20480    (32 rows x 72 stride)
// Bsl [2][2304]  @25088
#define SM_ASH 0
#define SM_ASL 10240
#define SM_BSH 20480
#define SM_BSL 25088
#define SM_TOTAL_EL 29696
#define TG_SMEM_BYTES (SM_TOTAL_EL * 2)

// C[M x 512] = A[M x K] @ B[K x 512], all operands bf16 hi/lo pairs.
// A rows r < Mu come from A1*, else A2* (row r-Mu). Outputs: bf16 hi/lo to
// C1*/C2* (nullable) and fp32 to C1f/C2f (nullable). grid.z = split-K slice.
__global__ __launch_bounds__(256) void k_tgemm(
    const bf16* __restrict__ A1h, const bf16* __restrict__ A1l,
    const bf16* __restrict__ A2h, const bf16* __restrict__ A2l,
    int Mu, int Mtot, int lda,
    const bf16* __restrict__ Bhg, const bf16* __restrict__ Blg,
    bf16* C1h, bf16* C1l, bf16* C2h, bf16* C2l,
    float* C1f, float* C2f,
    int kper, int K)
{
    extern __shared__ __align__(16) bf16 smem[];
    uint32_t smb = (uint32_t)__cvta_generic_to_shared(smem);

    int tid = threadIdx.x;
    int lane = tid & 31, wid = tid >> 5;
    int wm = wid & 3, wn = wid >> 2;
    int row0 = blockIdx.y * 128, col0 = blockIdx.x * 64;
    int k0 = blockIdx.z * kper, k1 = k0 + kper; if (k1 > K) k1 = K;
    size_t coff = (size_t)blockIdx.z * Mtot * H_;

    float acc[2][4][4];
    #pragma unroll
    for (int a = 0; a < 2; a++)
        #pragma unroll
        for (int b = 0; b < 4; b++)
            #pragma unroll
            for (int c = 0; c < 4; c++) acc[a][b][c] = 0.f;

    // fragment lane addressing
    int a_r = (lane & 7) + (lane & 8);
    int a_c = (lane & 16) ? 8 : 0;
    // B (trans): regs come out {k0n0, k8n0, k0n8, k8n8}; contiguous pairs are
    // the correct mma B fragments for n-blocks 0 and 8.
    int b_r = (lane & 7) + (lane & 8);
    int b_c = (lane & 16) ? 8 : 0;

    // staging: A chunks (2/thread/buffer), B chunk (1/thread/buffer)
    int am0 = tid >> 2, ac8 = (tid & 3) * 8;      // chunk tid
    int sbk = tid >> 3, sbn = (tid & 7) * 8;      // B chunk

    int iters = (k1 - k0) >> 5;

    #define LOAD_STAGE(st, kt) do {                                              \
        _Pragma("unroll")                                                        \
        for (int p = 0; p < 2; p++) {                                            \
            int m = am0 + p * 64;                                                \
            int r = row0 + m;                                                    \
            bool ok = (r < Mtot);                                                \
            bool lo = ok && (r < Mu);                                            \
            size_t off = ok ? ((lo ? (size_t)r : (size_t)(r - Mu)) * lda         \
                               + (kt) + ac8) : 0;                                \
            const bf16* sh = lo ? A1h : A2h;                                     \
            const bf16* sl = lo ? A1l : A2l;                                     \
            int sz = ok ? 16 : 0;                                                \
            uint32_t d = (uint32_t)((st) * 5120 + m * 40 + ac8) * 2;             \
            cpa16(smb + (SM_ASH * 2) + d, sh + off, sz);                         \
            cpa16(smb + (SM_ASL * 2) + d, sl + off, sz);                         \
        }                                                                        \
        {                                                                        \
            size_t off = (size_t)((kt) + sbk) * H_ + col0 + sbn;                 \
            uint32_t d = (uint32_t)((st) * 2304 + sbk * 72 + sbn) * 2;           \
            cpa16(smb + (SM_BSH * 2) + d, Bhg + off, 16);                        \
            cpa16(smb + (SM_BSL * 2) + d, Blg + off, 16);                        \
        }                                                                        \
        cpa_commit();                                                            \
    } while (0)

    LOAD_STAGE(0, k0);

    for (int it = 0; it < iters; it++) {
        if (it + 1 < iters) {
            LOAD_STAGE((it + 1) & 1, k0 + ((it + 1) << 5));
            cpa_wait1();
        } else {
            cpa_wait0();
        }
        __syncthreads();
        int st = it & 1;
        const bf16* Ash = smem + SM_ASH + st * 5120;
        const bf16* Asl = smem + SM_ASL + st * 5120;
        const bf16* Bsh = smem + SM_BSH + st * 2304;
        const bf16* Bsl = smem + SM_BSL + st * 2304;

        #pragma unroll
        for (int ks = 0; ks < 2; ks++) {
            int kc = ks * 16;
            uint32_t ah[2][4], al[2][4], bh[2][4], bl[2][4];
            #pragma unroll
            for (int mt = 0; mt < 2; mt++) {
                int mr = wm * 32 + mt * 16 + a_r;
                ldsm4(ah[mt], Ash + mr * 40 + kc + a_c);
                ldsm4(al[mt], Asl + mr * 40 + kc + a_c);
            }
            #pragma unroll
            for (int pr = 0; pr < 2; pr++) {
                int nb = wn * 32 + pr * 16 + b_c;
                ldsm4t(bh[pr], Bsh + (kc + b_r) * 72 + nb);
                ldsm4t(bl[pr], Bsl + (kc + b_r) * 72 + nb);
            }
            #pragma unroll
            for (int mt = 0; mt < 2; mt++)
                #pragma unroll
                for (int nt = 0; nt < 4; nt++) {
                    const uint32_t* bhf = &bh[nt >> 1][(nt & 1) * 2];
                    const uint32_t* blf = &bl[nt >> 1][(nt & 1) * 2];
                    mma16816(acc[mt][nt], ah[mt], bhf);
                    mma16816(acc[mt][nt], ah[mt], blf);
                    mma16816(acc[mt][nt], al[mt], bhf);
                }
        }
        __syncthreads();
    }

    #pragma unroll
    for (int mt = 0; mt < 2; mt++)
        #pragma unroll
        for (int nt = 0; nt < 4; nt++) {
            int c = col0 + wn * 32 + nt * 8 + (lane & 3) * 2;
            #pragma unroll
            for (int half = 0; half < 2; half++) {
                int r = row0 + wm * 32 + mt * 16 + (lane >> 2) + half * 8;
                if (r >= Mtot) continue;
                float v0 = acc[mt][nt][half * 2], v1 = acc[mt][nt][half * 2 + 1];
                bool lo = (r < Mu);
                size_t ro = lo ? (size_t)r * H_ : (size_t)(r - Mu) * H_;
                bf16* ch = lo ? C1h : C2h;
                bf16* cl = lo ? C1l : C2l;
                float* cf = lo ? C1f : C2f;
                if (ch) {
                    splitw(v0, &ch[coff + ro + c], &cl[coff + ro + c]);
                    splitw(v1, &ch[coff + ro + c + 1], &cl[coff + ro + c + 1]);
                }
                if (cf) { cf[coff + ro + c] = v0; cf[coff + ro + c + 1] = v1; }
            }
        }
}

// ---------------------------------------------------------------------------
__device__ __forceinline__ void gridbar(int it) {
    __syncthreads();
    __threadfence();
    if (threadIdx.x == 0) {
        int t = atomicAdd(&g_cnt, 1);
        if (t == SCAN_BLOCKS - 1) {
            atomicExch(&g_cnt, 0);
            __threadfence();
            atomicAdd(&g_gen, 1);
        }
        while (*(volatile int*)&g_gen < it + 1) {}
    }
    __syncthreads();
}

// Horner scan: S = Z_15; for q=14..0: S = S@G + Z_q, G = A^16 (fp32).
__global__ __launch_bounds__(256) void k_scanall() {
    __shared__ float Ssm[4][H_];
    __shared__ float red[32][128];
    int tid = threadIdx.x;
    int bg = blockIdx.x >> 4;
    int hg = blockIdx.x & 15;
    int krep = tid >> 3;
    int hslot = tid & 7;
    int h = hg * 32 + hslot * 4;
    const float* gp = g_Gf + (size_t)(krep * 16) * H_ + h;

    for (int i = 0; i < 16; i++) {
        int q = 15 - i;
        float a0[4] = {}, a1[4] = {}, a2[4] = {}, a3[4] = {};
        if (i > 0) {
            const float* Sin = ((i - 1) & 1) ? g_S1 : g_S0;
            for (int t = tid; t < 4 * H_; t += 256)
                Ssm[t >> 9][t & 511] = Sin[(bg * 4 + (t >> 9)) * H_ + (t & 511)];
            __syncthreads();
            #pragma unroll 4
            for (int kk = 0; kk < 16; kk++) {
                int k = (kk + krep) & 15;   // stagger: kill Ssm bank conflicts
                float4 g = *(const float4*)(gp + (size_t)k * H_);
                float s0 = Ssm[0][krep * 16 + k];
                float s1 = Ssm[1][krep * 16 + k];
                float s2 = Ssm[2][krep * 16 + k];
                float s3 = Ssm[3][krep * 16 + k];
                a0[0] += s0 * g.x; a0[1] += s0 * g.y; a0[2] += s0 * g.z; a0[3] += s0 * g.w;
                a1[0] += s1 * g.x; a1[1] += s1 * g.y; a1[2] += s1 * g.z; a1[3] += s1 * g.w;
                a2[0] += s2 * g.x; a2[1] += s2 * g.y; a2[2] += s2 * g.z; a2[3] += s2 * g.w;
                a3[0] += s3 * g.x; a3[1] += s3 * g.y; a3[2] += s3 * g.z; a3[3] += s3 * g.w;
            }
        }
        *(float4*)&red[krep][0 * 32 + hslot * 4] = *(float4*)a0;
        *(float4*)&red[krep][1 * 32 + hslot * 4] = *(float4*)a1;
        *(float4*)&red[krep][2 * 32 + hslot * 4] = *(float4*)a2;
        *(float4*)&red[krep][3 * 32 + hslot * 4] = *(float4*)a3;
        __syncthreads();
        if (tid < 128) {
            float v = 0.f;
            #pragma unroll
            for (int s = 0; s < 32; s++) v += red[s][tid];
            int b = tid >> 5, hcl = tid & 31;
            int m = q * 16 + bg * 4 + b;
            int hc = hg * 32 + hcl;
            float z = 0.f;
            #pragma unroll
            for (int s2 = 0; s2 < NSPLIT; s2++)
                z += g_Zp[(size_t)s2 * (MZ * H_) + (size_t)m * H_ + hc];
            float* Sout = (i & 1) ? g_S1 : g_S0;
            Sout[(bg * 4 + b) * H_ + hc] = v + z;
        }
        if (i < 15) gridbar(i);
    }
}

// ---------------------------------------------------------------------------
__global__ void k_final(const float* __restrict__ S, const float* __restrict__ x,
                        const float* __restrict__ Wr, const float* __restrict__ br,
                        const float* __restrict__ lng, const float* __restrict__ lnb,
                        const float* __restrict__ W1, const float* __restrict__ b1,
                        const float* __restrict__ W2, const float* __restrict__ b2,
                        float* __restrict__ out) {
    int b = blockIdx.x, tid = threadIdx.x;
    __shared__ float xs[L_], z[H_], a[F_], r1[8], r2[8];
    __shared__ float mu_s, rs_s;
    if (tid < L_) xs[tid] = x[((size_t)b * T_ + (T_ - 1)) * L_ + tid];
    __syncthreads();
    for (int h = tid; h < H_; h += 256) {
        float acc = S[b * H_ + h] + br[h];
        for (int l = 0; l < L_; l++) acc += xs[l] * Wr[(size_t)l * H_ + h];
        z[h] = acc;
    }
    __syncthreads();
    float s1 = 0.f, s2 = 0.f;
    for (int h = tid; h < H_; h += 256) { float v = z[h]; s1 += v; s2 += v * v; }
    #pragma unroll
    for (int o = 16; o; o >>= 1) {
        s1 += __shfl_xor_sync(0xFFFFFFFFu, s1, o);
        s2 += __shfl_xor_sync(0xFFFFFFFFu, s2, o);
    }
    if ((tid & 31) == 0) { r1[tid >> 5] = s1; r2[tid >> 5] = s2; }
    __syncthreads();
    if (tid == 0) {
        float t1 = 0.f, t2 = 0.f;
        #pragma unroll
        for (int i = 0; i < 8; i++) { t1 += r1[i]; t2 += r2[i]; }
        float mu = t1 / (float)H_;
        mu_s = mu; rs_s = rsqrtf(t2 / (float)H_ - mu * mu + 1e-5f);
    }
    __syncthreads();
    for (int h = tid; h < H_; h += 256) z[h] = (z[h] - mu_s) * rs_s * lng[h] + lnb[h];
    __syncthreads();
    for (int f = tid; f < F_; f += 256) {
        float acc = b1[f];
        for (int h = 0; h < H_; h++) acc += z[h] * W1[(size_t)h * F_ + f];
        a[f] = fmaxf(acc, 0.f);
    }
    __syncthreads();
    for (int h2 = tid; h2 < H_; h2 += 256) {
        float acc = b2[h2];
        for (int f = 0; f < F_; f++) acc += a[f] * W2[(size_t)f * H_ + h2];
        out[b * H_ + h2] = acc;
    }
}

// ---------------------------------------------------------------------------
extern "C" void kernel_launch(void* const* d_in, const int* in_sizes, int n_in,
                              void* d_out, int out_size) {
    const float* x   = (const float*)d_in[0];
    const float* We  = (const float*)d_in[1];
    const float* be  = (const float*)d_in[2];
    const float* Wb  = (const float*)d_in[3];
    const float* A   = (const float*)d_in[4];
    const float* Wr  = (const float*)d_in[5];
    const float* br  = (const float*)d_in[6];
    const float* lng = (const float*)d_in[7];
    const float* lnb = (const float*)d_in[8];
    const float* W1  = (const float*)d_in[9];
    const float* b1  = (const float*)d_in[10];
    const float* W2  = (const float*)d_in[11];
    const float* b2  = (const float*)d_in[12];
    float* out = (float*)d_out;

    bf16 *A0h, *A0l, *Uh, *Ul, *Ph, *Pl, *Xh, *Xl;
    float *Gf, *Zp, *S1;
    cudaGetSymbolAddress((void**)&A0h, g_A0h);
    cudaGetSymbolAddress((void**)&A0l, g_A0l);
    cudaGetSymbolAddress((void**)&Uh,  g_Uh);
    cudaGetSymbolAddress((void**)&Ul,  g_Ul);
    cudaGetSymbolAddress((void**)&Ph,  g_Ph);
    cudaGetSymbolAddress((void**)&Pl,  g_Pl);
    cudaGetSymbolAddress((void**)&Xh,  g_Xh);
    cudaGetSymbolAddress((void**)&Xl,  g_Xl);
    cudaGetSymbolAddress((void**)&Gf,  g_Gf);
    cudaGetSymbolAddress((void**)&Zp,  g_Zp);
    cudaGetSymbolAddress((void**)&S1,  g_S1);

    bf16* P0h = Ph;               bf16* P0l = Pl;                // A^2
    bf16* P1h = Ph + H_ * H_;     bf16* P1l = Pl + H_ * H_;      // A^4
    bf16* P2h = Ph + 2 * H_ * H_; bf16* P2l = Pl + 2 * H_ * H_;  // A^8
    bf16* P3h = Ph + 3 * H_ * H_; bf16* P3l = Pl + 3 * H_ * H_;  // A^16

    static bool attr_set = false;
    if (!attr_set) {
        cudaFuncSetAttribute(k_tgemm, cudaFuncAttributeMaxDynamicSharedMemorySize,
                             TG_SMEM_BYTES);
        attr_set = true;
    }

    // merged prep: splitA + initW0 + gather + barrier init
    k_prep<<<1024 + 260 + 2080, 256>>>(A, We, be, Wb, x);

    // merged doubling + power chain: [U_new ; A^(2s)] = [U_prev ; A^s] @ A^s
    k_tgemm<<<dim3(8, 6), 256, TG_SMEM_BYTES>>>(Uh, Ul, A0h, A0l, 130, 642, H_,
        A0h, A0l, Uh + 130 * H_, Ul + 130 * H_, P0h, P0l, nullptr, nullptr, 512, 512);
    k_tgemm<<<dim3(8, 7), 256, TG_SMEM_BYTES>>>(Uh, Ul, P0h, P0l, 260, 772, H_,
        P0h, P0l, Uh + 260 * H_, Ul + 260 * H_, P1h, P1l, nullptr, nullptr, 512, 512);
    k_tgemm<<<dim3(8, 9), 256, TG_SMEM_BYTES>>>(Uh, Ul, P1h, P1l, 520, 1032, H_,
        P1h, P1l, Uh + 520 * H_, Ul + 520 * H_, P2h, P2l, nullptr, nullptr, 512, 512);
    k_tgemm<<<dim3(8, 13), 256, TG_SMEM_BYTES>>>(Uh, Ul, P2h, P2l, 1040, 1552, H_,
        P2h, P2l, Uh + 1040 * H_, Ul + 1040 * H_, P3h, P3l, nullptr, Gf, 512, 512);

    // Z = X @ U, split-K -> fp32 partials (consumed by the scan)
    k_tgemm<<<dim3(8, 2, NSPLIT), 256, TG_SMEM_BYTES>>>(Xh, Xl, Xh, Xl, MZ, MZ,
        KTOT, Uh, Ul, nullptr, nullptr, nullptr, nullptr, Zp, nullptr, KPER, KTOT);

    // single-launch Horner scan over q=15..0
    k_scanall<<<SCAN_BLOCKS, 256>>>();

    // after 16 iters (last i=15, odd) the state is in g_S1
    k_final<<<B_, 256>>>(S1, x, Wr, br, lng, lnb, W1, b1, W2, b2, out);
}

// round 7
// speedup vs baseline: 1.4957x; 1.4957x over previous
#include <cuda_runtime.h>
#include <cuda_bf16.h>
#include <cstdint>

#define B_ 16
#define T_ 2048
#define L_ 128
#define H_ 512
#define M_IN 256
#define F_ 1024
#define LP 130                 // U table row-block: 128 ch + 1 const + 1 pad
#define C_CHUNK 16
#define Q_CHUNK 16
#define KX 2048                // X k-width: 16 * 128 (no const row)
#define MZ (Q_CHUNK * B_)      // 256
#define NSPLIT 8
#define KPER 256
#define SCAN_BLOCKS 64

typedef __nv_bfloat16 bf16;

__device__ __align__(16) bf16 g_A0h[H_ * H_], g_A0l[H_ * H_];
__device__ __align__(16) bf16 g_Uh[C_CHUNK * LP * H_], g_Ul[C_CHUNK * LP * H_];
__device__ __align__(16) bf16 g_Ph[4 * H_ * H_], g_Pl[4 * H_ * H_];
__device__ __align__(16) bf16 g_Xh[MZ * KX], g_Xl[MZ * KX];
__device__ __align__(16) float g_Gf[H_ * H_];
__device__ __align__(16) float g_Zp[NSPLIT * MZ * H_];
__device__ __align__(16) float g_S0[B_ * H_], g_S1[B_ * H_];
__device__ int g_cnt;
__device__ int g_gen;

__device__ __forceinline__ void splitw(float v, bf16* ph, bf16* pl) {
    bf16 h = __float2bfloat16(v);
    *ph = h;
    *pl = __float2bfloat16(v - __bfloat162float(h));
}

// ------------------------- merged prep kernel ------------------------------
// blocks [0,1024): splitA; [1024,1284): initW0; [1284,3332): gather X
__global__ void k_prep(const float* __restrict__ A, const float* __restrict__ We,
                       const float* __restrict__ be, const float* __restrict__ Wb,
                       const float* __restrict__ x) {
    const int NB_A = (H_ * H_) / 256;          // 1024
    const int NB_W = (LP * H_ + 255) / 256;    // 260
    int bid = blockIdx.x, tid = threadIdx.x;
    if (bid == 0 && tid == 0) { g_cnt = 0; g_gen = 0; }
    if (bid < NB_A) {
        int i = bid * 256 + tid;
        splitw(A[i], &g_A0h[i], &g_A0l[i]);
    } else if (bid < NB_A + NB_W) {
        int i = (bid - NB_A) * 256 + tid;
        if (i >= LP * H_) return;
        int l = i >> 9, h = i & 511;
        float acc = 0.f;
        if (l < 128) { for (int m = 0; m < M_IN; m++) acc += We[l * M_IN + m] * Wb[m * H_ + h]; }
        else if (l == 128) { for (int m = 0; m < M_IN; m++) acc += be[m] * Wb[m * H_ + h]; }
        splitw(acc, &g_Uh[i], &g_Ul[i]);
    } else {
        int i = (bid - NB_A - NB_W) * 256 + tid;   // < MZ*KX = 524288
        int m = i >> 11, kk = i & 2047;
        int r = kk >> 7, l = kk & 127;
        int q = m >> 4, b = m & 15;
        float v = x[((size_t)b * T_ + (T_ - 1) - (q * C_CHUNK + r)) * L_ + l];
        splitw(v, &g_Xh[i], &g_Xl[i]);
    }
}

// ---------------------------------------------------------------------------
__device__ __forceinline__ void ldsm4(uint32_t* r, const void* p) {
    uint32_t addr = (uint32_t)__cvta_generic_to_shared(p);
    asm volatile("ldmatrix.sync.aligned.m8n8.x4.shared.b16 {%0,%1,%2,%3}, [%4];"
                 : "=r"(r[0]), "=r"(r[1]), "=r"(r[2]), "=r"(r[3]) : "r"(addr));
}
__device__ __forceinline__ void ldsm4t(uint32_t* r, const void* p) {
    uint32_t addr = (uint32_t)__cvta_generic_to_shared(p);
    asm volatile("ldmatrix.sync.aligned.m8n8.x4.trans.shared.b16 {%0,%1,%2,%3}, [%4];"
                 : "=r"(r[0]), "=r"(r[1]), "=r"(r[2]), "=r"(r[3]) : "r"(addr));
}
__device__ __forceinline__ void mma16816(float* d, const uint32_t* a, const uint32_t* b) {
    asm volatile("mma.sync.aligned.m16n8k16.row.col.f32.bf16.bf16.f32 "
                 "{%0,%1,%2,%3}, {%4,%5,%6,%7}, {%8,%9}, {%0,%1,%2,%3};"
                 : "+f"(d[0]), "+f"(d[1]), "+f"(d[2]), "+f"(d[3])
                 : "r"(a[0]), "r"(a[1]), "r"(a[2]), "r"(a[3]), "r"(b[0]), "r"(b[1]));
}

// C[M x 512] = A[M x K] @ B[K x 512], all operands bf16 hi/lo pairs.
// 64x64 tiles, 256 threads (8 warps: 2 m-slots x 4 n-slots of 16 cols).
// A rows r < Mu from A1*, else A2* (row r-Mu). Outputs: bf16 hi/lo to C1*/C2*
// (nullable) and fp32 to C1f/C2f (nullable). grid.z = split-K slice.
__global__ __launch_bounds__(256) void k_tgemm(
    const bf16* __restrict__ A1h, const bf16* __restrict__ A1l,
    const bf16* __restrict__ A2h, const bf16* __restrict__ A2l,
    int Mu, int Mtot, int lda,
    const bf16* __restrict__ Bhg, const bf16* __restrict__ Blg,
    bf16* C1h, bf16* C1l, bf16* C2h, bf16* C2l,
    float* C1f, float* C2f,
    int kper, int K)
{
    __shared__ __align__(16) bf16 Ash[64][40];
    __shared__ __align__(16) bf16 Asl[64][40];
    __shared__ __align__(16) bf16 Bsh[32][72];
    __shared__ __align__(16) bf16 Bsl[32][72];

    int tid = threadIdx.x;
    int lane = tid & 31, wid = tid >> 5;
    int wm = wid & 1, wn = wid >> 1;
    int row0 = blockIdx.y * 64, col0 = blockIdx.x * 64;
    int k0 = blockIdx.z * kper, k1 = k0 + kper; if (k1 > K) k1 = K;
    size_t coff = (size_t)blockIdx.z * Mtot * H_;

    float acc[2][2][4];
    #pragma unroll
    for (int a = 0; a < 2; a++)
        #pragma unroll
        for (int b = 0; b < 2; b++)
            #pragma unroll
            for (int c = 0; c < 4; c++) acc[a][b][c] = 0.f;

    // fragment lane addressing
    int a_r = (lane & 7) + (lane & 8);
    int a_c = (lane & 16) ? 8 : 0;
    // B (trans): regs {k0n0, k8n0, k0n8, k8n8}; contiguous pairs = mma B frags
    int b_r = (lane & 7) + (lane & 8);
    int b_c = (lane & 16) ? 8 : 0;

    // staging: A 64x32 = 256 uint4, B 32x64 = 256 uint4; 1 each per thread
    int am = tid >> 2, ac8 = (tid & 3) * 8;
    int sbk = tid >> 3, sbn = (tid & 7) * 8;

    // precompute A source row pointer (row fixed across k)
    int ar_g = row0 + am;
    bool a_ok = (ar_g < Mtot);
    bool a_lo = a_ok && (ar_g < Mu);
    const bf16* ash_src = a_ok ? ((a_lo ? A1h : A2h) + (size_t)(a_lo ? ar_g : ar_g - Mu) * lda + ac8) : nullptr;
    const bf16* asl_src = a_ok ? ((a_lo ? A1l : A2l) + (size_t)(a_lo ? ar_g : ar_g - Mu) * lda + ac8) : nullptr;
    const bf16* bsh_src = Bhg + (size_t)sbk * H_ + col0 + sbn;
    const bf16* bsl_src = Blg + (size_t)sbk * H_ + col0 + sbn;

    for (int kt = k0; kt < k1; kt += 32) {
        uint4 vh = make_uint4(0, 0, 0, 0), vl = vh;
        if (a_ok) {
            vh = *(const uint4*)(ash_src + kt);
            vl = *(const uint4*)(asl_src + kt);
        }
        *(uint4*)&Ash[am][ac8] = vh;
        *(uint4*)&Asl[am][ac8] = vl;
        *(uint4*)&Bsh[sbk][sbn] = *(const uint4*)(bsh_src + (size_t)kt * H_);
        *(uint4*)&Bsl[sbk][sbn] = *(const uint4*)(bsl_src + (size_t)kt * H_);
        __syncthreads();

        #pragma unroll
        for (int ks = 0; ks < 2; ks++) {
            int kc = ks * 16;
            uint32_t ah[2][4], al[2][4], bh[4], bl[4];
            #pragma unroll
            for (int mt = 0; mt < 2; mt++) {
                int mr = wm * 32 + mt * 16 + a_r;
                ldsm4(ah[mt], &Ash[mr][kc + a_c]);
                ldsm4(al[mt], &Asl[mr][kc + a_c]);
            }
            {
                int nb = wn * 16 + b_c;
                ldsm4t(bh, &Bsh[kc + b_r][nb]);
                ldsm4t(bl, &Bsl[kc + b_r][nb]);
            }
            #pragma unroll
            for (int mt = 0; mt < 2; mt++)
                #pragma unroll
                for (int nt = 0; nt < 2; nt++) {
                    const uint32_t* bhf = &bh[nt * 2];
                    const uint32_t* blf = &bl[nt * 2];
                    mma16816(acc[mt][nt], ah[mt], bhf);
                    mma16816(acc[mt][nt], ah[mt], blf);
                    mma16816(acc[mt][nt], al[mt], bhf);
                }
        }
        __syncthreads();
    }

    #pragma unroll
    for (int mt = 0; mt < 2; mt++)
        #pragma unroll
        for (int nt = 0; nt < 2; nt++) {
            int c = col0 + wn * 16 + nt * 8 + (lane & 3) * 2;
            #pragma unroll
            for (int half = 0; half < 2; half++) {
                int r = row0 + wm * 32 + mt * 16 + (lane >> 2) + half * 8;
                if (r >= Mtot) continue;
                float v0 = acc[mt][nt][half * 2], v1 = acc[mt][nt][half * 2 + 1];
                bool lo = (r < Mu);
                size_t ro = lo ? (size_t)r * H_ : (size_t)(r - Mu) * H_;
                bf16* ch = lo ? C1h : C2h;
                bf16* cl = lo ? C1l : C2l;
                float* cf = lo ? C1f : C2f;
                if (ch) {
                    splitw(v0, &ch[coff + ro + c], &cl[coff + ro + c]);
                    splitw(v1, &ch[coff + ro + c + 1], &cl[coff + ro + c + 1]);
                }
                if (cf) { cf[coff + ro + c] = v0; cf[coff + ro + c + 1] = v1; }
            }
        }
}

// ---------------------------------------------------------------------------
__device__ __forceinline__ void gridbar(int it) {
    __syncthreads();
    __threadfence();
    if (threadIdx.x == 0) {
        int t = atomicAdd(&g_cnt, 1);
        if (t == SCAN_BLOCKS - 1) {
            atomicExch(&g_cnt, 0);
            __threadfence();
            atomicAdd(&g_gen, 1);
        }
        while (*(volatile int*)&g_gen < it + 1) {}
    }
    __syncthreads();
}

// Horner scan: S = Z_15+bias; for q=14..0: S = S@G + Z_q + bias  (G = A^16).
// bias[h] = sum_{r<16} U[r*130+128][h]  (the be@Wb row propagated through A^r)
__global__ __launch_bounds__(256) void k_scanall() {
    __shared__ float Ssm[4][H_];
    __shared__ float red[32][128];
    __shared__ float bias[32];
    int tid = threadIdx.x;
    int bg = blockIdx.x >> 4;
    int hg = blockIdx.x & 15;
    int krep = tid >> 3;
    int hslot = tid & 7;
    int h = hg * 32 + hslot * 4;
    const float* gp = g_Gf + (size_t)(krep * 16) * H_ + h;

    if (tid < 32) {
        int hc = hg * 32 + tid;
        float s = 0.f;
        #pragma unroll
        for (int r = 0; r < C_CHUNK; r++) {
            size_t off = (size_t)(r * LP + 128) * H_ + hc;
            s += __bfloat162float(g_Uh[off]) + __bfloat162float(g_Ul[off]);
        }
        bias[tid] = s;
    }
    __syncthreads();

    for (int i = 0; i < 16; i++) {
        int q = 15 - i;
        float a0[4] = {}, a1[4] = {}, a2[4] = {}, a3[4] = {};
        if (i > 0) {
            const float* Sin = ((i - 1) & 1) ? g_S1 : g_S0;
            for (int t = tid; t < 4 * H_; t += 256)
                Ssm[t >> 9][t & 511] = Sin[(bg * 4 + (t >> 9)) * H_ + (t & 511)];
            __syncthreads();
            #pragma unroll 4
            for (int kk = 0; kk < 16; kk++) {
                int k = (kk + krep) & 15;   // stagger: kill Ssm bank conflicts
                float4 g = *(const float4*)(gp + (size_t)k * H_);
                float s0 = Ssm[0][krep * 16 + k];
                float s1 = Ssm[1][krep * 16 + k];
                float s2 = Ssm[2][krep * 16 + k];
                float s3 = Ssm[3][krep * 16 + k];
                a0[0] += s0 * g.x; a0[1] += s0 * g.y; a0[2] += s0 * g.z; a0[3] += s0 * g.w;
                a1[0] += s1 * g.x; a1[1] += s1 * g.y; a1[2] += s1 * g.z; a1[3] += s1 * g.w;
                a2[0] += s2 * g.x; a2[1] += s2 * g.y; a2[2] += s2 * g.z; a2[3] += s2 * g.w;
                a3[0] += s3 * g.x; a3[1] += s3 * g.y; a3[2] += s3 * g.z; a3[3] += s3 * g.w;
            }
        }
        *(float4*)&red[krep][0 * 32 + hslot * 4] = *(float4*)a0;
        *(float4*)&red[krep][1 * 32 + hslot * 4] = *(float4*)a1;
        *(float4*)&red[krep][2 * 32 + hslot * 4] = *(float4*)a2;
        *(float4*)&red[krep][3 * 32 + hslot * 4] = *(float4*)a3;
        __syncthreads();
        if (tid < 128) {
            float v = 0.f;
            #pragma unroll
            for (int s = 0; s < 32; s++) v += red[s][tid];
            int b = tid >> 5, hcl = tid & 31;
            int m = q * 16 + bg * 4 + b;
            int hc = hg * 32 + hcl;
            float z = bias[hcl];
            #pragma unroll
            for (int s2 = 0; s2 < NSPLIT; s2++)
                z += g_Zp[(size_t)s2 * (MZ * H_) + (size_t)m * H_ + hc];
            float* Sout = (i & 1) ? g_S1 : g_S0;
            Sout[(bg * 4 + b) * H_ + hc] = v + z;
        }
        if (i < 15) gridbar(i);
    }
}

// ---------------------------------------------------------------------------
__global__ void k_final(const float* __restrict__ S, const float* __restrict__ x,
                        const float* __restrict__ Wr, const float* __restrict__ br,
                        const float* __restrict__ lng, const float* __restrict__ lnb,
                        const float* __restrict__ W1, const float* __restrict__ b1,
                        const float* __restrict__ W2, const float* __restrict__ b2,
                        float* __restrict__ out) {
    int b = blockIdx.x, tid = threadIdx.x;
    __shared__ float xs[L_], z[H_], a[F_], r1[8], r2[8];
    __shared__ float mu_s, rs_s;
    if (tid < L_) xs[tid] = x[((size_t)b * T_ + (T_ - 1)) * L_ + tid];
    __syncthreads();
    for (int h = tid; h < H_; h += 256) {
        float acc = S[b * H_ + h] + br[h];
        for (int l = 0; l < L_; l++) acc += xs[l] * Wr[(size_t)l * H_ + h];
        z[h] = acc;
    }
    __syncthreads();
    float s1 = 0.f, s2 = 0.f;
    for (int h = tid; h < H_; h += 256) { float v = z[h]; s1 += v; s2 += v * v; }
    #pragma unroll
    for (int o = 16; o; o >>= 1) {
        s1 += __shfl_xor_sync(0xFFFFFFFFu, s1, o);
        s2 += __shfl_xor_sync(0xFFFFFFFFu, s2, o);
    }
    if ((tid & 31) == 0) { r1[tid >> 5] = s1; r2[tid >> 5] = s2; }
    __syncthreads();
    if (tid == 0) {
        float t1 = 0.f, t2 = 0.f;
        #pragma unroll
        for (int i = 0; i < 8; i++) { t1 += r1[i]; t2 += r2[i]; }
        float mu = t1 / (float)H_;
        mu_s = mu; rs_s = rsqrtf(t2 / (float)H_ - mu * mu + 1e-5f);
    }
    __syncthreads();
    for (int h = tid; h < H_; h += 256) z[h] = (z[h] - mu_s) * rs_s * lng[h] + lnb[h];
    __syncthreads();
    for (int f = tid; f < F_; f += 256) {
        float acc = b1[f];
        for (int h = 0; h < H_; h++) acc += z[h] * W1[(size_t)h * F_ + f];
        a[f] = fmaxf(acc, 0.f);
    }
    __syncthreads();
    for (int h2 = tid; h2 < H_; h2 += 256) {
        float acc = b2[h2];
        for (int f = 0; f < F_; f++) acc += a[f] * W2[(size_t)f * H_ + h2];
        out[b * H_ + h2] = acc;
    }
}

// ---------------------------------------------------------------------------
extern "C" void kernel_launch(void* const* d_in, const int* in_sizes, int n_in,
                              void* d_out, int out_size) {
    const float* x   = (const float*)d_in[0];
    const float* We  = (const float*)d_in[1];
    const float* be  = (const float*)d_in[2];
    const float* Wb  = (const float*)d_in[3];
    const float* A   = (const float*)d_in[4];
    const float* Wr  = (const float*)d_in[5];
    const float* br  = (const float*)d_in[6];
    const float* lng = (const float*)d_in[7];
    const float* lnb = (const float*)d_in[8];
    const float* W1  = (const float*)d_in[9];
    const float* b1  = (const float*)d_in[10];
    const float* W2  = (const float*)d_in[11];
    const float* b2  = (const float*)d_in[12];
    float* out = (float*)d_out;

    bf16 *A0h, *A0l, *Uh, *Ul, *Ph, *Pl, *Xh, *Xl;
    float *Gf, *Zp, *S1;
    cudaGetSymbolAddress((void**)&A0h, g_A0h);
    cudaGetSymbolAddress((void**)&A0l, g_A0l);
    cudaGetSymbolAddress((void**)&Uh,  g_Uh);
    cudaGetSymbolAddress((void**)&Ul,  g_Ul);
    cudaGetSymbolAddress((void**)&Ph,  g_Ph);
    cudaGetSymbolAddress((void**)&Pl,  g_Pl);
    cudaGetSymbolAddress((void**)&Xh,  g_Xh);
    cudaGetSymbolAddress((void**)&Xl,  g_Xl);
    cudaGetSymbolAddress((void**)&Gf,  g_Gf);
    cudaGetSymbolAddress((void**)&Zp,  g_Zp);
    cudaGetSymbolAddress((void**)&S1,  g_S1);

    bf16* P0h = Ph;               bf16* P0l = Pl;                // A^2
    bf16* P1h = Ph + H_ * H_;     bf16* P1l = Pl + H_ * H_;      // A^4
    bf16* P2h = Ph + 2 * H_ * H_; bf16* P2l = Pl + 2 * H_ * H_;  // A^8
    bf16* P3h = Ph + 3 * H_ * H_; bf16* P3l = Pl + 3 * H_ * H_;  // A^16

    // merged prep: splitA + initW0 + gather + barrier init
    k_prep<<<1024 + 260 + 2048, 256>>>(A, We, be, Wb, x);

    // merged doubling + power chain: [U_new ; A^(2s)] = [U_prev ; A^s] @ A^s
    k_tgemm<<<dim3(8, 11), 256>>>(Uh, Ul, A0h, A0l, 130, 642, H_, A0h, A0l,
        Uh + 130 * H_, Ul + 130 * H_, P0h, P0l, nullptr, nullptr, 512, 512);
    k_tgemm<<<dim3(8, 13), 256>>>(Uh, Ul, P0h, P0l, 260, 772, H_, P0h, P0l,
        Uh + 260 * H_, Ul + 260 * H_, P1h, P1l, nullptr, nullptr, 512, 512);
    k_tgemm<<<dim3(8, 17), 256>>>(Uh, Ul, P1h, P1l, 520, 1032, H_, P1h, P1l,
        Uh + 520 * H_, Ul + 520 * H_, P2h, P2l, nullptr, nullptr, 512, 512);
    k_tgemm<<<dim3(8, 25), 256>>>(Uh, Ul, P2h, P2l, 1040, 1552, H_, P2h, P2l,
        Uh + 1040 * H_, Ul + 1040 * H_, P3h, P3l, nullptr, Gf, 512, 512);

    // Z = X[256x2048] @ Ux (U without const rows): use strided view of U via
    // per-row mapping: row kk = r*128+l maps to U row r*130+l. Achieved by
    // passing lda=... not expressible -> instead bake mapping into B operand:
    // B here is U, indexed by k; we reindex k inside the loads by launching
    // with K=KX and remapping in a dedicated wrapper below.
    // Simpler: zgemm's B rows are U rows r*130+l; since kt is a multiple of 32
    // and l in [0,128), each 32-k chunk lies within one r-block, so
    // B row for k = (k>>7)*130 + (k&127).
    // Implemented via the same kernel by passing Bhg/Blg = U and a flag is
    // overkill; we use a small dedicated kernel:
    {
        extern __global__ void k_zgemm();
        k_zgemm<<<dim3(8, 4, NSPLIT), 256>>>();
    }

    // single-launch Horner scan over q=15..0
    k_scanall<<<SCAN_BLOCKS, 256>>>();

    // after 16 iters (last i=15, odd) the state is in g_S1
    k_final<<<B_, 256>>>(S1, x, Wr, br, lng, lnb, W1, b1, W2, b2, out);
}

// Z = X[256 x 2048] @ U' where U' row k = U row (k>>7)*130 + (k&127).
// 64x64 tiles, split-K: slice z covers k in [z*256, z*256+256).
__global__ __launch_bounds__(256) void k_zgemm() {
    __shared__ __align__(16) bf16 Ash[64][40];
    __shared__ __align__(16) bf16 Asl[64][40];
    __shared__ __align__(16) bf16 Bsh[32][72];
    __shared__ __align__(16) bf16 Bsl[32][72];

    int tid = threadIdx.x;
    int lane = tid & 31, wid = tid >> 5;
    int wm = wid & 1, wn = wid >> 1;
    int row0 = blockIdx.y * 64, col0 = blockIdx.x * 64;
    int k0 = blockIdx.z * KPER;
    size_t coff = (size_t)blockIdx.z * MZ * H_;

    float acc[2][2][4];
    #pragma unroll
    for (int a = 0; a < 2; a++)
        #pragma unroll
        for (int b = 0; b < 2; b++)
            #pragma unroll
            for (int c = 0; c < 4; c++) acc[a][b][c] = 0.f;

    int a_r = (lane & 7) + (lane & 8);
    int a_c = (lane & 16) ? 8 : 0;
    int b_r = (lane & 7) + (lane & 8);
    int b_c = (lane & 16) ? 8 : 0;

    int am = tid >> 2, ac8 = (tid & 3) * 8;
    int sbk = tid >> 3, sbn = (tid & 7) * 8;

    const bf16* ash_src = g_Xh + (size_t)(row0 + am) * KX + ac8;
    const bf16* asl_src = g_Xl + (size_t)(row0 + am) * KX + ac8;

    for (int kt = k0; kt < k0 + KPER; kt += 32) {
        *(uint4*)&Ash[am][ac8] = *(const uint4*)(ash_src + kt);
        *(uint4*)&Asl[am][ac8] = *(const uint4*)(asl_src + kt);
        int kg = kt + sbk;
        size_t brow = (size_t)((kg >> 7) * LP + (kg & 127)) * H_ + col0 + sbn;
        *(uint4*)&Bsh[sbk][sbn] = *(const uint4*)(g_Uh + brow);
        *(uint4*)&Bsl[sbk][sbn] = *(const uint4*)(g_Ul + brow);
        __syncthreads();

        #pragma unroll
        for (int ks = 0; ks < 2; ks++) {
            int kc = ks * 16;
            uint32_t ah[2][4], al[2][4], bh[4], bl[4];
            #pragma unroll
            for (int mt = 0; mt < 2; mt++) {
                int mr = wm * 32 + mt * 16 + a_r;
                ldsm4(ah[mt], &Ash[mr][kc + a_c]);
                ldsm4(al[mt], &Asl[mr][kc + a_c]);
            }
            {
                int nb = wn * 16 + b_c;
                ldsm4t(bh, &Bsh[kc + b_r][nb]);
                ldsm4t(bl, &Bsl[kc + b_r][nb]);
            }
            #pragma unroll
            for (int mt = 0; mt < 2; mt++)
                #pragma unroll
                for (int nt = 0; nt < 2; nt++) {
                    const uint32_t* bhf = &bh[nt * 2];
                    const uint32_t* blf = &bl[nt * 2];
                    mma16816(acc[mt][nt], ah[mt], bhf);
                    mma16816(acc[mt][nt], ah[mt], blf);
                    mma16816(acc[mt][nt], al[mt], bhf);
                }
        }
        __syncthreads();
    }

    #pragma unroll
    for (int mt = 0; mt < 2; mt++)
        #pragma unroll
        for (int nt = 0; nt < 2; nt++) {
            int c = col0 + wn * 16 + nt * 8 + (lane & 3) * 2;
            #pragma unroll
            for (int half = 0; half < 2; half++) {
                int r = row0 + wm * 32 + mt * 16 + (lane >> 2) + half * 8;
                float* cp = g_Zp + coff + (size_t)r * H_ + c;
                cp[0] = acc[mt][nt][half * 2];
                cp[1] = acc[mt][nt][half * 2 + 1];
            }
        }
}